// round 1
// baseline (speedup 1.0000x reference)
#include <cuda_runtime.h>

// Padded coeff grid: (1024 + 2*PAD) x (1024 + 2*PAD), PAD=2
#define GROWS 1028
#define GCOLS 1028

// Expanded layout: g_exp[r*GCOLS + c] = {coeffs[r,c], coeffs[r,c+1], coeffs[r,c+2], coeffs[r,c+3]}
// 1028*1028*16B = ~16.9 MB, fits comfortably in 126MB L2.
__device__ float4 g_exp[GROWS * GCOLS];

__global__ void expand_kernel(const float* __restrict__ coeffs) {
    int idx = blockIdx.x * blockDim.x + threadIdx.x;
    if (idx >= GROWS * GCOLS) return;
    int r = idx / GCOLS;
    int c = idx - r * GCOLS;
    const float* row = coeffs + r * GCOLS;
    float4 v;
    v.x = __ldg(&row[c]);
    v.y = (c + 1 < GCOLS) ? __ldg(&row[c + 1]) : 0.0f;
    v.z = (c + 2 < GCOLS) ? __ldg(&row[c + 2]) : 0.0f;
    v.w = (c + 3 < GCOLS) ? __ldg(&row[c + 3]) : 0.0f;
    g_exp[idx] = v;
}

__device__ __forceinline__ void bspline_w(float t, float w[4]) {
    // j=-1: (1-t)^3
    // j= 0: (3t-6)t^2 + 4
    // j= 1: -(3t+3)(t-1)^2 + 4
    // j= 2: t^3
    float omt = 1.0f - t;
    w[0] = omt * omt * omt;
    w[1] = (3.0f * t - 6.0f) * t * t + 4.0f;
    float tm1 = t - 1.0f;
    w[2] = -(3.0f * t + 3.0f) * tm1 * tm1 + 4.0f;
    w[3] = t * t * t;
}

__global__ void __launch_bounds__(256) spline_kernel(
    const float2* __restrict__ x, float* __restrict__ out, int n)
{
    int i = blockIdx.x * blockDim.x + threadIdx.x;
    if (i >= n) return;

    float2 p = __ldg(&x[i]);
    // xn = (x - omega_lo)/h - 0.5 = x*1024 - 0.5
    float xn0 = p.x * 1024.0f - 0.5f;
    float xn1 = p.y * 1024.0f - 0.5f;

    bool valid = (xn0 > -2.0f) && (xn0 < 1024.0f) && (xn1 > -2.0f) && (xn1 < 1024.0f);

    float P0 = floorf(xn0);
    float P1 = floorf(xn1);
    float t0 = xn0 - P0;
    float t1 = xn1 - P1;

    float w0[4], w1[4];
    bspline_w(t0, w0);
    bspline_w(t1, w1);

    // stencil top-left in padded grid: row = PAD + P0 - 1, col = PAD + P1 - 1
    int r0 = (int)P0 + 1;
    int c0 = (int)P1 + 1;
    // safety clamps (never fire for in-domain inputs)
    r0 = min(max(r0, 0), GROWS - 4);
    c0 = min(max(c0, 0), GCOLS - 4);

    const float4* base = g_exp + (long)r0 * GCOLS + c0;

    // Issue all 4 row-gathers up front for MLP
    float4 v0 = __ldg(base + 0 * GCOLS);
    float4 v1 = __ldg(base + 1 * GCOLS);
    float4 v2 = __ldg(base + 2 * GCOLS);
    float4 v3 = __ldg(base + 3 * GCOLS);

    float s0 = fmaf(v0.x, w1[0], fmaf(v0.y, w1[1], fmaf(v0.z, w1[2], v0.w * w1[3])));
    float s1 = fmaf(v1.x, w1[0], fmaf(v1.y, w1[1], fmaf(v1.z, w1[2], v1.w * w1[3])));
    float s2 = fmaf(v2.x, w1[0], fmaf(v2.y, w1[1], fmaf(v2.z, w1[2], v2.w * w1[3])));
    float s3 = fmaf(v3.x, w1[0], fmaf(v3.y, w1[1], fmaf(v3.z, w1[2], v3.w * w1[3])));

    float acc = fmaf(s0, w0[0], fmaf(s1, w0[1], fmaf(s2, w0[2], s3 * w0[3])));

    out[i] = valid ? acc : 0.0f;
}

extern "C" void kernel_launch(void* const* d_in, const int* in_sizes, int n_in,
                              void* d_out, int out_size) {
    const float2* x = (const float2*)d_in[0];     // [N,2] float32
    const float* coeffs = (const float*)d_in[1];  // [1028,1028] float32
    float* out = (float*)d_out;                   // [N,1] float32
    int n = out_size;                             // 2097152

    int total = GROWS * GCOLS;
    expand_kernel<<<(total + 255) / 256, 256>>>(coeffs);
    spline_kernel<<<(n + 255) / 256, 256>>>(x, out, n);
}